// round 14
// baseline (speedup 1.0000x reference)
#include <cuda_runtime.h>
#include <cuda_bf16.h>
#include <cuda_fp16.h>
#include <math.h>

// ---------------- problem constants ----------------
#define Dv 512
#define Nv 16384          // B*H*W
#define Kv 2048
#define DELTA 0.02f       // > 2x (bf16 mma error 7.8e-3 + fp16 store error ~1e-3)
#define CSLOTS 16         // per-row candidate slots (E[cand]~3; overflow -> full rescan)

// d_out layout (floats)
#define OFF_Q    0ULL
#define OFF_DP   8388608ULL
#define OFF_CL   41943040ULL
#define OFF_LOSS 41943041ULL
#define OFF_CBS  41943042ULL
#define OFF_EMB  41943043ULL
#define OFF_NNEW 42991619ULL
#define OFF_ZAVG 42993667ULL

typedef unsigned long long u64;
typedef unsigned int u32;

// ---------------- scratch ----------------
__device__ float g_znorm_rm[(size_t)Nv * Dv];   // [N][D]  (rescue, gather_q, zavg)
__device__ float g_cb_rm[(size_t)Kv * Dv];      // [K][D]  (rescue)
__device__ __nv_bfloat16 g_ah[(size_t)Nv * Dv]; // bf16(z_norm) row-major
__device__ __nv_bfloat16 g_bh[(size_t)Kv * Dv]; // bf16(cb_norm) row-major
__device__ float g_zsq[Nv];
__device__ float g_cbsq[Kv];
__device__ __half g_logh[(size_t)Nv * Kv];      // shifted dist-2, fp16 (67MB)
__device__ int   g_candk[(size_t)Nv * CSLOTS];  // per-row candidate codes
__device__ int   g_ccnt[Nv];                    // per-row candidate counts
__device__ float g_thr[Nv];                     // per-row approx min
__device__ int   g_idx[Nv];
__device__ float g_ntotal[Kv];
__device__ int   g_off[Kv];
__device__ int   g_cursor[Kv];
__device__ int   g_tok[Nv];
__device__ float g_commit;
__device__ float g_cbsum;
__device__ float g_nsum;

// ---------------- normalize codebook (+ per-code counter init) ----------------
__global__ void __launch_bounds__(128) k_normalize_cb(const float* __restrict__ emb) {
    __shared__ float red[128];
    __shared__ float sinv;
    const int k = blockIdx.x;
    const int t = threadIdx.x;
    if (t == 0) { g_ntotal[k] = 0.0f; g_cursor[k] = 0; }
    if (k == 0 && t == 1) { g_commit = 0.0f; g_cbsum = 0.0f; }
    const float4 v = *((const float4*)(emb + (size_t)k * Dv) + t);
    red[t] = v.x * v.x + v.y * v.y + v.z * v.z + v.w * v.w;
    __syncthreads();
    for (int s = 64; s > 0; s >>= 1) {
        if (t < s) red[t] += red[t + s];
        __syncthreads();
    }
    if (t == 0) {
        float s = red[0];
        float iv = 1.0f / fmaxf(sqrtf(s), 1e-12f);
        sinv = iv;
        g_cbsq[k] = s * iv * iv;
    }
    __syncthreads();
    const float iv = sinv;
    float x0 = v.x * iv, x1 = v.y * iv, x2 = v.z * iv, x3 = v.w * iv;
    size_t base = (size_t)k * Dv + 4 * t;
    *(float4*)(g_cb_rm + base) = make_float4(x0, x1, x2, x3);
    __nv_bfloat162 h01 = __floats2bfloat162_rn(x0, x1);
    __nv_bfloat162 h23 = __floats2bfloat162_rn(x2, x3);
    *(uint2*)(g_bh + base) = make_uint2(*(u32*)&h01, *(u32*)&h23);
}

// ---------------- normalize z -> znorm_rm [N][D], bf16 rows, zsq (+ ccnt init) ----------------
__global__ void __launch_bounds__(256) k_normalize_z(const float* __restrict__ z) {
    extern __shared__ float s[];   // [512][33] raw values, s[d*33 + w]
    __shared__ float ssb[256];
    __shared__ float inv[32];
    const int bid = blockIdx.x;
    const int b = bid >> 5, h = bid & 31;
    const int t = threadIdx.x;
    const int w = t & 31, dg = t >> 5;
    const int n0 = bid << 5;
    if (t < 32) g_ccnt[n0 + t] = 0;
    const float* zp = z + (size_t)b * 524288 + h * 32 + w;
    float ss = 0.0f;
#pragma unroll 8
    for (int i = 0; i < 64; i++) {
        int d = dg + (i << 3);
        float v = zp[(size_t)d * 1024];
        s[d * 33 + w] = v;
        ss += v * v;
    }
    ssb[t] = ss;
    __syncthreads();
    if (t < 32) {
        float sum = 0.0f;
#pragma unroll
        for (int g = 0; g < 8; g++) sum += ssb[(g << 5) + t];
        float iv = 1.0f / fmaxf(sqrtf(sum), 1e-12f);
        inv[t] = iv;
        g_zsq[n0 + t] = sum * iv * iv;
    }
    __syncthreads();
    const int nl = t >> 7;
    const int c4 = t & 127;
    const int d0 = c4 << 2;
#pragma unroll 1
    for (int nb = 0; nb < 16; nb++) {
        int n_loc = nb * 2 + nl;
        float ivn = inv[n_loc];
        float x0 = s[(d0 + 0) * 33 + n_loc] * ivn;
        float x1 = s[(d0 + 1) * 33 + n_loc] * ivn;
        float x2 = s[(d0 + 2) * 33 + n_loc] * ivn;
        float x3 = s[(d0 + 3) * 33 + n_loc] * ivn;
        size_t base = (size_t)(n0 + n_loc) * Dv + d0;
        *(float4*)(g_znorm_rm + base) = make_float4(x0, x1, x2, x3);
        __nv_bfloat162 h01 = __floats2bfloat162_rn(x0, x1);
        __nv_bfloat162 h23 = __floats2bfloat162_rn(x2, x3);
        *(uint2*)(g_ah + base) = make_uint2(*(u32*)&h01, *(u32*)&h23);
    }
}

// ---------------- mma.sync bf16 GEMM: 128x128 CTA tile, K=512, 3-stage cp.async (R8 best) ----------------
#define LDM(r0, r1, r2, r3, a) \
    asm volatile("ldmatrix.sync.aligned.m8n8.x4.shared.b16 {%0,%1,%2,%3}, [%4];" \
                 : "=r"(r0), "=r"(r1), "=r"(r2), "=r"(r3) : "r"(a))
#define MMA(c, a, b0, b1) \
    asm volatile("mma.sync.aligned.m16n8k16.row.col.f32.bf16.bf16.f32 " \
                 "{%0,%1,%2,%3},{%4,%5,%6,%7},{%8,%9},{%0,%1,%2,%3};" \
                 : "+f"(c[0]), "+f"(c[1]), "+f"(c[2]), "+f"(c[3]) \
                 : "r"(a[0]), "r"(a[1]), "r"(a[2]), "r"(a[3]), "r"(b0), "r"(b1))
#define STG_SZ 32768

__global__ void __launch_bounds__(256, 2) k_gemm() {
    extern __shared__ __align__(128) char sm[];
    const u32 sb = (u32)__cvta_generic_to_shared(sm);
    const int t = threadIdx.x;
    const int m0 = blockIdx.y << 7;
    const int n0 = blockIdx.x << 7;
    const int lane = t & 31, wid = t >> 5;
    const int wm = (wid >> 2) << 6;
    const int wn = (wid & 3) << 5;
    const int lrow = lane & 15, lsel = lane >> 4;
    const int r0 = t >> 3, g = t & 7;

    float acc[4][4][4];
#pragma unroll
    for (int i = 0; i < 4; i++)
#pragma unroll
        for (int j = 0; j < 4; j++)
#pragma unroll
            for (int e = 0; e < 4; e++) acc[i][j][e] = 0.0f;

    u32 dstRel[4];
    const __nv_bfloat16* srcA0 = g_ah + (size_t)(m0 + r0) * Dv + g * 8;
    const __nv_bfloat16* srcB0 = g_bh + (size_t)(n0 + r0) * Dv + g * 8;
#pragma unroll
    for (int i = 0; i < 4; i++) {
        int row = r0 + (i << 5);
        dstRel[i] = row * 128 + ((g ^ (row & 7)) << 4);
    }

    auto issue = [&](int c) {
        const u32 stage = sb + (u32)(c % 3) * STG_SZ;
        const size_t ksrc = (size_t)c * 64;
#pragma unroll
        for (int i = 0; i < 4; i++) {
            const __nv_bfloat16* sA = srcA0 + (size_t)(i << 5) * Dv + ksrc;
            const __nv_bfloat16* sB = srcB0 + (size_t)(i << 5) * Dv + ksrc;
            asm volatile("cp.async.cg.shared.global [%0], [%1], 16;"
                         :: "r"(stage + dstRel[i]), "l"(sA));
            asm volatile("cp.async.cg.shared.global [%0], [%1], 16;"
                         :: "r"(stage + 16384 + dstRel[i]), "l"(sB));
        }
        asm volatile("cp.async.commit_group;");
    };

    u32 abase[4], bbase[2];
#pragma unroll
    for (int i = 0; i < 4; i++) {
        int row = wm + i * 16 + lrow;
        abase[i] = sb + row * 128 + ((lsel ^ (row & 7)) << 4);
    }
#pragma unroll
    for (int jp = 0; jp < 2; jp++) {
        int row = wn + jp * 16 + lrow;
        bbase[jp] = sb + 16384 + row * 128 + ((lsel ^ (row & 7)) << 4);
    }

    issue(0);
    issue(1);

    u32 soff = 0;
#pragma unroll 1
    for (int c = 0; c < 8; c++) {
        if (c < 7) asm volatile("cp.async.wait_group 1;");
        else       asm volatile("cp.async.wait_group 0;");
        __syncthreads();
        if (c < 6) issue(c + 2);
#pragma unroll
        for (int ks = 0; ks < 4; ks++) {
            const u32 kx = (u32)ks << 5;
            u32 br[2][4];
            u32 af[4][4];
            LDM(br[0][0], br[0][1], br[0][2], br[0][3], (bbase[0] + soff) ^ kx);
            LDM(br[1][0], br[1][1], br[1][2], br[1][3], (bbase[1] + soff) ^ kx);
            LDM(af[0][0], af[0][1], af[0][2], af[0][3], (abase[0] + soff) ^ kx);
            LDM(af[1][0], af[1][1], af[1][2], af[1][3], (abase[1] + soff) ^ kx);
            LDM(af[2][0], af[2][1], af[2][2], af[2][3], (abase[2] + soff) ^ kx);
            LDM(af[3][0], af[3][1], af[3][2], af[3][3], (abase[3] + soff) ^ kx);
#pragma unroll
            for (int i = 0; i < 4; i++) {
                MMA(acc[i][0], af[i], br[0][0], br[0][2]);
                MMA(acc[i][1], af[i], br[0][1], br[0][3]);
                MMA(acc[i][2], af[i], br[1][0], br[1][2]);
                MMA(acc[i][3], af[i], br[1][1], br[1][3]);
            }
        }
        soff += STG_SZ;
        if (soff == 3 * STG_SZ) soff = 0;
    }

    const int gid = lane >> 2, tid4 = lane & 3;
#pragma unroll
    for (int i = 0; i < 4; i++) {
        const int rowa = m0 + wm + i * 16 + gid;
        const float zs0 = g_zsq[rowa] - 2.0f;
        const float zs1 = g_zsq[rowa + 8] - 2.0f;
#pragma unroll
        for (int j = 0; j < 4; j++) {
            const int col = n0 + wn + j * 8 + tid4 * 2;
            const float cb0 = g_cbsq[col];
            const float cb1 = g_cbsq[col + 1];
            __half2 v0 = __floats2half2_rn(zs0 + cb0 - 2.0f * acc[i][j][0],
                                           zs0 + cb1 - 2.0f * acc[i][j][1]);
            __half2 v1 = __floats2half2_rn(zs1 + cb0 - 2.0f * acc[i][j][2],
                                           zs1 + cb1 - 2.0f * acc[i][j][3]);
            *(__half2*)(g_logh + (size_t)rowa * Kv + col) = v0;
            *(__half2*)(g_logh + (size_t)(rowa + 8) * Kv + col) = v1;
        }
    }
}

// ---------------- softmax + per-row candidate emission ----------------
__global__ void __launch_bounds__(256) k_softmax(float* __restrict__ dp) {
    __shared__ float wmin[8];
    __shared__ float wsum[8];
    const int n = blockIdx.x;
    const int t = threadIdx.x;
    const int lane = t & 31, warp = t >> 5;
    const __half* lr = g_logh + (size_t)n * Kv;

    uint4 raw = __ldg((const uint4*)(lr + t * 8));
    __half2 h0 = *(__half2*)&raw.x, h1 = *(__half2*)&raw.y;
    __half2 h2 = *(__half2*)&raw.z, h3 = *(__half2*)&raw.w;

    __half2 m2 = __hmin2(__hmin2(h0, h1), __hmin2(h2, h3));
    float bv = fminf(__low2float(m2), __high2float(m2));
#pragma unroll
    for (int o = 16; o > 0; o >>= 1)
        bv = fminf(bv, __shfl_xor_sync(0xFFFFFFFFu, bv, o));
    if (lane == 0) wmin[warp] = bv;
    __syncthreads();
    float dmin = wmin[0];
#pragma unroll
    for (int wI = 1; wI < 8; wI++) dmin = fminf(dmin, wmin[wI]);
    if (t == 0) g_thr[n] = dmin;

    float v[8];
    { float2 f = __half22float2(h0); v[0] = f.x; v[1] = f.y; }
    { float2 f = __half22float2(h1); v[2] = f.x; v[3] = f.y; }
    { float2 f = __half22float2(h2); v[4] = f.x; v[5] = f.y; }
    { float2 f = __half22float2(h3); v[6] = f.x; v[7] = f.y; }

    // per-row candidate emission for exact-argmin rescue
    const float thr = dmin + DELTA;
#pragma unroll
    for (int j = 0; j < 8; j++) {
        if (v[j] <= thr) {
            int slot = atomicAdd(&g_ccnt[n], 1);
            if (slot < CSLOTS) g_candk[(size_t)n * CSLOTS + slot] = t * 8 + j;
        }
    }

    float e[8];
    float ls = 0.0f;
#pragma unroll
    for (int j = 0; j < 8; j++) {
        e[j] = __expf(dmin - v[j]);
        ls += e[j];
    }
#pragma unroll
    for (int o = 16; o > 0; o >>= 1) ls += __shfl_xor_sync(0xFFFFFFFFu, ls, o);
    if (lane == 0) wsum[warp] = ls;
    __syncthreads();
    float tot = wsum[0];
#pragma unroll
    for (int wI = 1; wI < 8; wI++) tot += wsum[wI];
    const float rs = 1.0f / tot;

    float* out = dp + (size_t)n * Kv + t * 8;
    float4 o0 = make_float4(e[0] * rs, e[1] * rs, e[2] * rs, e[3] * rs);
    float4 o1 = make_float4(e[4] * rs, e[5] * rs, e[6] * rs, e[7] * rs);
    *(float4*)out = o0;
    *(float4*)(out + 4) = o1;
}

// ---------------- exact fp32 argmin rescue: one warp per row, z-row in registers ----------------
__global__ void __launch_bounds__(256) k_rescue() {
    const int lane = threadIdx.x & 31;
    const int warp = threadIdx.x >> 5;
    const int n = blockIdx.x * 8 + warp;

    const float4* zr = (const float4*)(g_znorm_rm + (size_t)n * Dv);
    float4 az[4];
#pragma unroll
    for (int j = 0; j < 4; j++) az[j] = zr[lane + j * 32];
    const float zsq_n = g_zsq[n];
    const int cnt = g_ccnt[n];
    u64 best = 0xFFFFFFFFFFFFFFFFULL;

    auto eval = [&](int k) {
        const float4* cr = (const float4*)(g_cb_rm + (size_t)k * Dv);
        float dot = 0.0f;
#pragma unroll
        for (int j = 0; j < 4; j++) {
            float4 b = cr[lane + j * 32];
            dot += az[j].x * b.x + az[j].y * b.y + az[j].z * b.z + az[j].w * b.w;
        }
#pragma unroll
        for (int o = 16; o > 0; o >>= 1) dot += __shfl_xor_sync(0xFFFFFFFFu, dot, o);
        float d = zsq_n + g_cbsq[k] - 2.0f * dot;
        u32 bits = __float_as_uint(d);
        bits ^= (bits & 0x80000000u) ? 0xFFFFFFFFu : 0x80000000u;   // order-preserving
        u64 key = ((u64)bits << 32) | (u64)k;
        if (key < best) best = key;
    };

    if (cnt <= CSLOTS) {
        for (int i = 0; i < cnt; i++) eval(g_candk[(size_t)n * CSLOTS + i]);
    } else {
        // overflow (practically never): re-filter the full fp16 logit row
        const float thr = g_thr[n] + DELTA;
        const __half* lr = g_logh + (size_t)n * Kv;
        for (int k0 = 0; k0 < Kv; k0 += 32) {
            float v = __half2float(lr[k0 + lane]);
            u32 mask = __ballot_sync(0xFFFFFFFFu, v <= thr);
            while (mask) {
                int b = __ffs(mask) - 1;
                mask &= mask - 1;
                eval(k0 + b);
            }
        }
    }
    if (lane == 0) {
        int k = (int)(best & 0xFFFFFFFFULL);
        g_idx[n] = k;
        atomicAdd(&g_ntotal[k], 1.0f);
    }
}

// ---------------- fused N_new + sum + exclusive prefix (single block) ----------------
__global__ void __launch_bounds__(1024) k_stats(float* __restrict__ nnew_out,
                                                const float* __restrict__ nbuf) {
    __shared__ float red[1024];
    __shared__ float sp[1024];
    int t = threadIdx.x;
    float s = 0.0f;
#pragma unroll
    for (int j = 0; j < 2; j++) {
        int k = t + (j << 10);
        float v = 0.99f * nbuf[k] + 0.01f * g_ntotal[k];
        nnew_out[k] = v;
        s += v;
    }
    red[t] = s;
    __syncthreads();
    for (int st = 512; st > 0; st >>= 1) {
        if (t < st) red[t] += red[t + st];
        __syncthreads();
    }
    if (t == 0) g_nsum = red[0];
    float a = g_ntotal[2 * t], b = g_ntotal[2 * t + 1];
    float tsum = a + b;
    sp[t] = tsum;
    __syncthreads();
    for (int d = 1; d < 1024; d <<= 1) {
        float v = (t >= d) ? sp[t - d] : 0.0f;
        __syncthreads();
        sp[t] += v;
        __syncthreads();
    }
    float excl = sp[t] - tsum;
    g_off[2 * t]     = (int)excl;
    g_off[2 * t + 1] = (int)(excl + a);
}

// ---------------- bucket token ids by code ----------------
__global__ void k_fill() {
    int n = blockIdx.x * 256 + threadIdx.x;
    int k = g_idx[n];
    int pos = atomicAdd(&g_cursor[k], 1);
    g_tok[g_off[k] + pos] = n;
}

// ---------------- fused z_avg_new + embeddings_new + codebook_sum ----------------
__global__ void __launch_bounds__(512) k_zavg_emb(float* __restrict__ zavg_out,
                                                  const float* __restrict__ zavg_in,
                                                  float* __restrict__ emb_out,
                                                  const float* __restrict__ nnew) {
    __shared__ float red[512];
    const int k = blockIdx.x, t = threadIdx.x;
    const int cnt = (int)g_ntotal[k];
    const int off = g_off[k];
    float acc = 0.0f;
#pragma unroll 4
    for (int i = 0; i < cnt; i++) {
        int n = g_tok[off + i];
        acc += g_znorm_rm[(size_t)n * Dv + t];
    }
    const size_t gi = (size_t)k * Dv + t;
    float za = 0.99f * zavg_in[gi] + 0.01f * acc;
    zavg_out[gi] = za;
    float nn = nnew[k];
    float nsum = g_nsum;
    float wgt = (nn + 1e-5f) / (nsum + 0.02048f) * nsum;
    float e = za / wgt;
    emb_out[gi] = e;
    red[t] = fabsf(e);
    __syncthreads();
    for (int s = 256; s > 0; s >>= 1) {
        if (t < s) red[t] += red[t + s];
        __syncthreads();
    }
    if (t == 0) atomicAdd(&g_cbsum, red[0]);
}

// ---------------- q gather via smem transpose + commitment loss ----------------
__global__ void __launch_bounds__(256) k_gather_q(float* __restrict__ q) {
    extern __shared__ float e[];           // [32][513]
    __shared__ int kidx[32];
    __shared__ float red[256];
    const int bid = blockIdx.x;
    const int b = bid >> 5, h = bid & 31;
    const int t = threadIdx.x;
    const int n0 = bid << 5;
    if (t < 32) kidx[t] = g_idx[n0 + t];
    __syncthreads();
    float local = 0.0f;
#pragma unroll 4
    for (int it = 0; it < 16; it++) {
        int idx = t + it * 256;
        int r = idx >> 7;
        int c4 = idx & 127;
        float4 ev = ((const float4*)(g_znorm_rm + (size_t)kidx[r] * Dv))[c4];
        float4 zv = ((const float4*)(g_znorm_rm + (size_t)(n0 + r) * Dv))[c4];
        float dx = zv.x - ev.x, dy = zv.y - ev.y, dz = zv.z - ev.z, dw = zv.w - ev.w;
        local += dx * dx + dy * dy + dz * dz + dw * dw;
        float* er = e + r * 513 + c4 * 4;
        er[0] = ev.x; er[1] = ev.y; er[2] = ev.z; er[3] = ev.w;
    }
    red[t] = local;
    __syncthreads();
    for (int s = 128; s > 0; s >>= 1) {
        if (t < s) red[t] += red[t + s];
        __syncthreads();
    }
    if (t == 0) atomicAdd(&g_commit, red[0]);
    const int w = t & 31, dg = t >> 5;
    float* qp = q + (size_t)b * 524288 + h * 32 + w;
#pragma unroll 8
    for (int i = 0; i < 64; i++) {
        int d = dg + (i << 3);
        qp[(size_t)d * 1024] = e[w * 513 + d];
    }
}

__global__ void k_finalize(float* __restrict__ out) {
    float c = g_commit * (1.0f / 8388608.0f);
    out[OFF_CL]   = c;
    out[OFF_LOSS] = 0.25f * c;
    out[OFF_CBS]  = g_cbsum;
}

// ---------------- launch ----------------
extern "C" void kernel_launch(void* const* d_in, const int* in_sizes, int n_in,
                              void* d_out, int out_size) {
    const float* z    = (const float*)d_in[0];
    const float* emb  = (const float*)d_in[1];
    const float* nbuf = (const float*)d_in[2];
    const float* zavg = (const float*)d_in[3];
    float* out = (float*)d_out;

    float* q_out    = out + OFF_Q;
    float* dp_out   = out + OFF_DP;
    float* emb_out  = out + OFF_EMB;
    float* nnew_out = out + OFF_NNEW;
    float* zavg_out = out + OFF_ZAVG;

    cudaFuncSetAttribute(k_gemm, cudaFuncAttributeMaxDynamicSharedMemorySize, 3 * STG_SZ);
    cudaFuncSetAttribute(k_normalize_z, cudaFuncAttributeMaxDynamicSharedMemorySize, 67584);
    cudaFuncSetAttribute(k_gather_q, cudaFuncAttributeMaxDynamicSharedMemorySize, 65664);

    k_normalize_cb<<<Kv, 128>>>(emb);
    k_normalize_z<<<512, 256, 67584>>>(z);
    k_gemm<<<dim3(16, 128), 256, 3 * STG_SZ>>>();
    k_softmax<<<Nv, 256>>>(dp_out);
    k_rescue<<<Nv / 8, 256>>>();
    k_stats<<<1, 1024>>>(nnew_out, nbuf);
    k_fill<<<64, 256>>>();
    k_zavg_emb<<<Kv, 512>>>(zavg_out, zavg, emb_out, nnew_out);
    k_gather_q<<<512, 256, 65664>>>(q_out);
    k_finalize<<<1, 1>>>(out);
}

// round 15
// speedup vs baseline: 1.0638x; 1.0638x over previous
#include <cuda_runtime.h>
#include <cuda_bf16.h>
#include <cuda_fp16.h>
#include <math.h>

// ---------------- problem constants ----------------
#define Dv 512
#define Nv 16384          // B*H*W
#define Kv 2048
#define DELTA 0.02f       // > 2x (bf16 mma error 7.8e-3 + fp16 store error ~1e-3)
#define CSLOTS 16         // per-row candidate slots (E[cand]~3; overflow -> full rescan)

// d_out layout (floats)
#define OFF_Q    0ULL
#define OFF_DP   8388608ULL
#define OFF_CL   41943040ULL
#define OFF_LOSS 41943041ULL
#define OFF_CBS  41943042ULL
#define OFF_EMB  41943043ULL
#define OFF_NNEW 42991619ULL
#define OFF_ZAVG 42993667ULL

typedef unsigned long long u64;
typedef unsigned int u32;

// ---------------- scratch ----------------
__device__ float g_znorm_rm[(size_t)Nv * Dv];   // [N][D]  (rescue, gather_q, zavg)
__device__ float g_cb_rm[(size_t)Kv * Dv];      // [K][D]  (rescue)
__device__ __nv_bfloat16 g_ah[(size_t)Nv * Dv]; // bf16(z_norm) row-major
__device__ __nv_bfloat16 g_bh[(size_t)Kv * Dv]; // bf16(cb_norm) row-major
__device__ float g_zsq[Nv];
__device__ float g_cbsq[Kv];
__device__ __half g_logh[(size_t)Nv * Kv];      // shifted dist-2, fp16 (67MB)
__device__ int   g_candk[(size_t)Nv * CSLOTS];  // per-row candidate codes
__device__ int   g_ccnt[Nv];                    // per-row candidate counts
__device__ float g_thr[Nv];                     // per-row approx min
__device__ int   g_idx[Nv];
__device__ float g_ntotal[Kv];
__device__ int   g_off[Kv];
__device__ int   g_cursor[Kv];
__device__ int   g_tok[Nv];
__device__ float g_commit;
__device__ float g_cbsum;
__device__ float g_nsum;

// ---------------- normalize codebook (+ per-code counter init) ----------------
__global__ void __launch_bounds__(128) k_normalize_cb(const float* __restrict__ emb) {
    __shared__ float red[128];
    __shared__ float sinv;
    const int k = blockIdx.x;
    const int t = threadIdx.x;
    if (t == 0) { g_ntotal[k] = 0.0f; g_cursor[k] = 0; }
    if (k == 0 && t == 1) { g_commit = 0.0f; g_cbsum = 0.0f; }
    const float4 v = *((const float4*)(emb + (size_t)k * Dv) + t);
    red[t] = v.x * v.x + v.y * v.y + v.z * v.z + v.w * v.w;
    __syncthreads();
    for (int s = 64; s > 0; s >>= 1) {
        if (t < s) red[t] += red[t + s];
        __syncthreads();
    }
    if (t == 0) {
        float s = red[0];
        float iv = 1.0f / fmaxf(sqrtf(s), 1e-12f);
        sinv = iv;
        g_cbsq[k] = s * iv * iv;
    }
    __syncthreads();
    const float iv = sinv;
    float x0 = v.x * iv, x1 = v.y * iv, x2 = v.z * iv, x3 = v.w * iv;
    size_t base = (size_t)k * Dv + 4 * t;
    *(float4*)(g_cb_rm + base) = make_float4(x0, x1, x2, x3);
    __nv_bfloat162 h01 = __floats2bfloat162_rn(x0, x1);
    __nv_bfloat162 h23 = __floats2bfloat162_rn(x2, x3);
    *(uint2*)(g_bh + base) = make_uint2(*(u32*)&h01, *(u32*)&h23);
}

// ---------------- normalize z -> znorm_rm [N][D], bf16 rows, zsq (+ ccnt init) ----------------
__global__ void __launch_bounds__(256) k_normalize_z(const float* __restrict__ z) {
    extern __shared__ float s[];   // [512][33] raw values, s[d*33 + w]
    __shared__ float ssb[256];
    __shared__ float inv[32];
    const int bid = blockIdx.x;
    const int b = bid >> 5, h = bid & 31;
    const int t = threadIdx.x;
    const int w = t & 31, dg = t >> 5;
    const int n0 = bid << 5;
    if (t < 32) g_ccnt[n0 + t] = 0;
    const float* zp = z + (size_t)b * 524288 + h * 32 + w;
    float ss = 0.0f;
#pragma unroll 8
    for (int i = 0; i < 64; i++) {
        int d = dg + (i << 3);
        float v = zp[(size_t)d * 1024];
        s[d * 33 + w] = v;
        ss += v * v;
    }
    ssb[t] = ss;
    __syncthreads();
    if (t < 32) {
        float sum = 0.0f;
#pragma unroll
        for (int g = 0; g < 8; g++) sum += ssb[(g << 5) + t];
        float iv = 1.0f / fmaxf(sqrtf(sum), 1e-12f);
        inv[t] = iv;
        g_zsq[n0 + t] = sum * iv * iv;
    }
    __syncthreads();
    const int nl = t >> 7;
    const int c4 = t & 127;
    const int d0 = c4 << 2;
#pragma unroll 1
    for (int nb = 0; nb < 16; nb++) {
        int n_loc = nb * 2 + nl;
        float ivn = inv[n_loc];
        float x0 = s[(d0 + 0) * 33 + n_loc] * ivn;
        float x1 = s[(d0 + 1) * 33 + n_loc] * ivn;
        float x2 = s[(d0 + 2) * 33 + n_loc] * ivn;
        float x3 = s[(d0 + 3) * 33 + n_loc] * ivn;
        size_t base = (size_t)(n0 + n_loc) * Dv + d0;
        *(float4*)(g_znorm_rm + base) = make_float4(x0, x1, x2, x3);
        __nv_bfloat162 h01 = __floats2bfloat162_rn(x0, x1);
        __nv_bfloat162 h23 = __floats2bfloat162_rn(x2, x3);
        *(uint2*)(g_ah + base) = make_uint2(*(u32*)&h01, *(u32*)&h23);
    }
}

// ---------------- mma.sync bf16 GEMM: 128x128 CTA tile, K=512, 3-stage cp.async (R8 best) ----------------
#define LDM(r0, r1, r2, r3, a) \
    asm volatile("ldmatrix.sync.aligned.m8n8.x4.shared.b16 {%0,%1,%2,%3}, [%4];" \
                 : "=r"(r0), "=r"(r1), "=r"(r2), "=r"(r3) : "r"(a))
#define MMA(c, a, b0, b1) \
    asm volatile("mma.sync.aligned.m16n8k16.row.col.f32.bf16.bf16.f32 " \
                 "{%0,%1,%2,%3},{%4,%5,%6,%7},{%8,%9},{%0,%1,%2,%3};" \
                 : "+f"(c[0]), "+f"(c[1]), "+f"(c[2]), "+f"(c[3]) \
                 : "r"(a[0]), "r"(a[1]), "r"(a[2]), "r"(a[3]), "r"(b0), "r"(b1))
#define STG_SZ 32768

__global__ void __launch_bounds__(256, 2) k_gemm() {
    extern __shared__ __align__(128) char sm[];
    const u32 sb = (u32)__cvta_generic_to_shared(sm);
    const int t = threadIdx.x;
    const int m0 = blockIdx.y << 7;
    const int n0 = blockIdx.x << 7;
    const int lane = t & 31, wid = t >> 5;
    const int wm = (wid >> 2) << 6;
    const int wn = (wid & 3) << 5;
    const int lrow = lane & 15, lsel = lane >> 4;
    const int r0 = t >> 3, g = t & 7;

    float acc[4][4][4];
#pragma unroll
    for (int i = 0; i < 4; i++)
#pragma unroll
        for (int j = 0; j < 4; j++)
#pragma unroll
            for (int e = 0; e < 4; e++) acc[i][j][e] = 0.0f;

    u32 dstRel[4];
    const __nv_bfloat16* srcA0 = g_ah + (size_t)(m0 + r0) * Dv + g * 8;
    const __nv_bfloat16* srcB0 = g_bh + (size_t)(n0 + r0) * Dv + g * 8;
#pragma unroll
    for (int i = 0; i < 4; i++) {
        int row = r0 + (i << 5);
        dstRel[i] = row * 128 + ((g ^ (row & 7)) << 4);
    }

    auto issue = [&](int c) {
        const u32 stage = sb + (u32)(c % 3) * STG_SZ;
        const size_t ksrc = (size_t)c * 64;
#pragma unroll
        for (int i = 0; i < 4; i++) {
            const __nv_bfloat16* sA = srcA0 + (size_t)(i << 5) * Dv + ksrc;
            const __nv_bfloat16* sB = srcB0 + (size_t)(i << 5) * Dv + ksrc;
            asm volatile("cp.async.cg.shared.global [%0], [%1], 16;"
                         :: "r"(stage + dstRel[i]), "l"(sA));
            asm volatile("cp.async.cg.shared.global [%0], [%1], 16;"
                         :: "r"(stage + 16384 + dstRel[i]), "l"(sB));
        }
        asm volatile("cp.async.commit_group;");
    };

    u32 abase[4], bbase[2];
#pragma unroll
    for (int i = 0; i < 4; i++) {
        int row = wm + i * 16 + lrow;
        abase[i] = sb + row * 128 + ((lsel ^ (row & 7)) << 4);
    }
#pragma unroll
    for (int jp = 0; jp < 2; jp++) {
        int row = wn + jp * 16 + lrow;
        bbase[jp] = sb + 16384 + row * 128 + ((lsel ^ (row & 7)) << 4);
    }

    issue(0);
    issue(1);

    u32 soff = 0;
#pragma unroll 1
    for (int c = 0; c < 8; c++) {
        if (c < 7) asm volatile("cp.async.wait_group 1;");
        else       asm volatile("cp.async.wait_group 0;");
        __syncthreads();
        if (c < 6) issue(c + 2);
#pragma unroll
        for (int ks = 0; ks < 4; ks++) {
            const u32 kx = (u32)ks << 5;
            u32 br[2][4];
            u32 af[4][4];
            LDM(br[0][0], br[0][1], br[0][2], br[0][3], (bbase[0] + soff) ^ kx);
            LDM(br[1][0], br[1][1], br[1][2], br[1][3], (bbase[1] + soff) ^ kx);
            LDM(af[0][0], af[0][1], af[0][2], af[0][3], (abase[0] + soff) ^ kx);
            LDM(af[1][0], af[1][1], af[1][2], af[1][3], (abase[1] + soff) ^ kx);
            LDM(af[2][0], af[2][1], af[2][2], af[2][3], (abase[2] + soff) ^ kx);
            LDM(af[3][0], af[3][1], af[3][2], af[3][3], (abase[3] + soff) ^ kx);
#pragma unroll
            for (int i = 0; i < 4; i++) {
                MMA(acc[i][0], af[i], br[0][0], br[0][2]);
                MMA(acc[i][1], af[i], br[0][1], br[0][3]);
                MMA(acc[i][2], af[i], br[1][0], br[1][2]);
                MMA(acc[i][3], af[i], br[1][1], br[1][3]);
            }
        }
        soff += STG_SZ;
        if (soff == 3 * STG_SZ) soff = 0;
    }

    const int gid = lane >> 2, tid4 = lane & 3;
#pragma unroll
    for (int i = 0; i < 4; i++) {
        const int rowa = m0 + wm + i * 16 + gid;
        const float zs0 = g_zsq[rowa] - 2.0f;
        const float zs1 = g_zsq[rowa + 8] - 2.0f;
#pragma unroll
        for (int j = 0; j < 4; j++) {
            const int col = n0 + wn + j * 8 + tid4 * 2;
            const float cb0 = g_cbsq[col];
            const float cb1 = g_cbsq[col + 1];
            __half2 v0 = __floats2half2_rn(zs0 + cb0 - 2.0f * acc[i][j][0],
                                           zs0 + cb1 - 2.0f * acc[i][j][1]);
            __half2 v1 = __floats2half2_rn(zs1 + cb0 - 2.0f * acc[i][j][2],
                                           zs1 + cb1 - 2.0f * acc[i][j][3]);
            *(__half2*)(g_logh + (size_t)rowa * Kv + col) = v0;
            *(__half2*)(g_logh + (size_t)(rowa + 8) * Kv + col) = v1;
        }
    }
}

// ---------------- softmax + per-row candidate emission (streaming dp stores) ----------------
__global__ void __launch_bounds__(256) k_softmax(float* __restrict__ dp) {
    __shared__ float wmin[8];
    __shared__ float wsum[8];
    const int n = blockIdx.x;
    const int t = threadIdx.x;
    const int lane = t & 31, warp = t >> 5;
    const __half* lr = g_logh + (size_t)n * Kv;

    uint4 raw = __ldg((const uint4*)(lr + t * 8));
    __half2 h0 = *(__half2*)&raw.x, h1 = *(__half2*)&raw.y;
    __half2 h2 = *(__half2*)&raw.z, h3 = *(__half2*)&raw.w;

    __half2 m2 = __hmin2(__hmin2(h0, h1), __hmin2(h2, h3));
    float bv = fminf(__low2float(m2), __high2float(m2));
#pragma unroll
    for (int o = 16; o > 0; o >>= 1)
        bv = fminf(bv, __shfl_xor_sync(0xFFFFFFFFu, bv, o));
    if (lane == 0) wmin[warp] = bv;
    __syncthreads();
    float dmin = wmin[0];
#pragma unroll
    for (int wI = 1; wI < 8; wI++) dmin = fminf(dmin, wmin[wI]);
    if (t == 0) g_thr[n] = dmin;

    float v[8];
    { float2 f = __half22float2(h0); v[0] = f.x; v[1] = f.y; }
    { float2 f = __half22float2(h1); v[2] = f.x; v[3] = f.y; }
    { float2 f = __half22float2(h2); v[4] = f.x; v[5] = f.y; }
    { float2 f = __half22float2(h3); v[6] = f.x; v[7] = f.y; }

    const float thr = dmin + DELTA;
#pragma unroll
    for (int j = 0; j < 8; j++) {
        if (v[j] <= thr) {
            int slot = atomicAdd(&g_ccnt[n], 1);
            if (slot < CSLOTS) g_candk[(size_t)n * CSLOTS + slot] = t * 8 + j;
        }
    }

    float e[8];
    float ls = 0.0f;
#pragma unroll
    for (int j = 0; j < 8; j++) {
        e[j] = __expf(dmin - v[j]);
        ls += e[j];
    }
#pragma unroll
    for (int o = 16; o > 0; o >>= 1) ls += __shfl_xor_sync(0xFFFFFFFFu, ls, o);
    if (lane == 0) wsum[warp] = ls;
    __syncthreads();
    float tot = wsum[0];
#pragma unroll
    for (int wI = 1; wI < 8; wI++) tot += wsum[wI];
    const float rs = 1.0f / tot;

    float* out = dp + (size_t)n * Kv + t * 8;
    float4 o0 = make_float4(e[0] * rs, e[1] * rs, e[2] * rs, e[3] * rs);
    float4 o1 = make_float4(e[4] * rs, e[5] * rs, e[6] * rs, e[7] * rs);
    __stcs((float4*)out, o0);
    __stcs((float4*)(out + 4), o1);
}

// ---------------- exact fp32 argmin rescue: one warp per row, z-row in registers ----------------
__global__ void __launch_bounds__(256) k_rescue() {
    const int lane = threadIdx.x & 31;
    const int warp = threadIdx.x >> 5;
    const int n = blockIdx.x * 8 + warp;

    const float4* zr = (const float4*)(g_znorm_rm + (size_t)n * Dv);
    float4 az[4];
#pragma unroll
    for (int j = 0; j < 4; j++) az[j] = zr[lane + j * 32];
    const float zsq_n = g_zsq[n];
    const int cnt = g_ccnt[n];
    u64 best = 0xFFFFFFFFFFFFFFFFULL;

    auto eval = [&](int k) {
        const float4* cr = (const float4*)(g_cb_rm + (size_t)k * Dv);
        float dot = 0.0f;
#pragma unroll
        for (int j = 0; j < 4; j++) {
            float4 b = cr[lane + j * 32];
            dot += az[j].x * b.x + az[j].y * b.y + az[j].z * b.z + az[j].w * b.w;
        }
#pragma unroll
        for (int o = 16; o > 0; o >>= 1) dot += __shfl_xor_sync(0xFFFFFFFFu, dot, o);
        float d = zsq_n + g_cbsq[k] - 2.0f * dot;
        u32 bits = __float_as_uint(d);
        bits ^= (bits & 0x80000000u) ? 0xFFFFFFFFu : 0x80000000u;   // order-preserving
        u64 key = ((u64)bits << 32) | (u64)k;
        if (key < best) best = key;
    };

    if (cnt <= CSLOTS) {
        for (int i = 0; i < cnt; i++) eval(g_candk[(size_t)n * CSLOTS + i]);
    } else {
        const float thr = g_thr[n] + DELTA;
        const __half* lr = g_logh + (size_t)n * Kv;
        for (int k0 = 0; k0 < Kv; k0 += 32) {
            float v = __half2float(lr[k0 + lane]);
            u32 mask = __ballot_sync(0xFFFFFFFFu, v <= thr);
            while (mask) {
                int b = __ffs(mask) - 1;
                mask &= mask - 1;
                eval(k0 + b);
            }
        }
    }
    if (lane == 0) {
        int k = (int)(best & 0xFFFFFFFFULL);
        g_idx[n] = k;
        atomicAdd(&g_ntotal[k], 1.0f);
    }
}

// ---------------- fused N_new + sum + exclusive prefix (single block) ----------------
__global__ void __launch_bounds__(1024) k_stats(float* __restrict__ nnew_out,
                                                const float* __restrict__ nbuf) {
    __shared__ float red[1024];
    __shared__ float sp[1024];
    int t = threadIdx.x;
    float s = 0.0f;
#pragma unroll
    for (int j = 0; j < 2; j++) {
        int k = t + (j << 10);
        float v = 0.99f * nbuf[k] + 0.01f * g_ntotal[k];
        nnew_out[k] = v;
        s += v;
    }
    red[t] = s;
    __syncthreads();
    for (int st = 512; st > 0; st >>= 1) {
        if (t < st) red[t] += red[t + st];
        __syncthreads();
    }
    if (t == 0) g_nsum = red[0];
    float a = g_ntotal[2 * t], b = g_ntotal[2 * t + 1];
    float tsum = a + b;
    sp[t] = tsum;
    __syncthreads();
    for (int d = 1; d < 1024; d <<= 1) {
        float v = (t >= d) ? sp[t - d] : 0.0f;
        __syncthreads();
        sp[t] += v;
        __syncthreads();
    }
    float excl = sp[t] - tsum;
    g_off[2 * t]     = (int)excl;
    g_off[2 * t + 1] = (int)(excl + a);
}

// ---------------- bucket token ids by code ----------------
__global__ void k_fill() {
    int n = blockIdx.x * 256 + threadIdx.x;
    int k = g_idx[n];
    int pos = atomicAdd(&g_cursor[k], 1);
    g_tok[g_off[k] + pos] = n;
}

// ---------------- fused z_avg_new + embeddings_new + codebook_sum ----------------
__global__ void __launch_bounds__(512) k_zavg_emb(float* __restrict__ zavg_out,
                                                  const float* __restrict__ zavg_in,
                                                  float* __restrict__ emb_out,
                                                  const float* __restrict__ nnew) {
    __shared__ float red[512];
    const int k = blockIdx.x, t = threadIdx.x;
    const int cnt = (int)g_ntotal[k];
    const int off = g_off[k];
    float acc = 0.0f;
#pragma unroll 4
    for (int i = 0; i < cnt; i++) {
        int n = g_tok[off + i];
        acc += g_znorm_rm[(size_t)n * Dv + t];
    }
    const size_t gi = (size_t)k * Dv + t;
    float za = 0.99f * zavg_in[gi] + 0.01f * acc;
    zavg_out[gi] = za;
    float nn = nnew[k];
    float nsum = g_nsum;
    float wgt = (nn + 1e-5f) / (nsum + 0.02048f) * nsum;
    float e = za / wgt;
    emb_out[gi] = e;
    red[t] = fabsf(e);
    __syncthreads();
    for (int s = 256; s > 0; s >>= 1) {
        if (t < s) red[t] += red[t + s];
        __syncthreads();
    }
    if (t == 0) atomicAdd(&g_cbsum, red[0]);
}

// ---------------- q gather via smem transpose + commitment loss ----------------
__global__ void __launch_bounds__(256) k_gather_q(float* __restrict__ q) {
    extern __shared__ float e[];           // [32][513]
    __shared__ int kidx[32];
    __shared__ float red[256];
    const int bid = blockIdx.x;
    const int b = bid >> 5, h = bid & 31;
    const int t = threadIdx.x;
    const int n0 = bid << 5;
    if (t < 32) kidx[t] = g_idx[n0 + t];
    __syncthreads();
    float local = 0.0f;
#pragma unroll 4
    for (int it = 0; it < 16; it++) {
        int idx = t + it * 256;
        int r = idx >> 7;
        int c4 = idx & 127;
        float4 ev = ((const float4*)(g_znorm_rm + (size_t)kidx[r] * Dv))[c4];
        float4 zv = ((const float4*)(g_znorm_rm + (size_t)(n0 + r) * Dv))[c4];
        float dx = zv.x - ev.x, dy = zv.y - ev.y, dz = zv.z - ev.z, dw = zv.w - ev.w;
        local += dx * dx + dy * dy + dz * dz + dw * dw;
        float* er = e + r * 513 + c4 * 4;
        er[0] = ev.x; er[1] = ev.y; er[2] = ev.z; er[3] = ev.w;
    }
    red[t] = local;
    __syncthreads();
    for (int s = 128; s > 0; s >>= 1) {
        if (t < s) red[t] += red[t + s];
        __syncthreads();
    }
    if (t == 0) atomicAdd(&g_commit, red[0]);
    const int w = t & 31, dg = t >> 5;
    float* qp = q + (size_t)b * 524288 + h * 32 + w;
#pragma unroll 8
    for (int i = 0; i < 64; i++) {
        int d = dg + (i << 3);
        qp[(size_t)d * 1024] = e[w * 513 + d];
    }
}

__global__ void k_finalize(float* __restrict__ out) {
    float c = g_commit * (1.0f / 8388608.0f);
    out[OFF_CL]   = c;
    out[OFF_LOSS] = 0.25f * c;
    out[OFF_CBS]  = g_cbsum;
}

// ---------------- launch (with cross-stream forks for independent stages) ----------------
extern "C" void kernel_launch(void* const* d_in, const int* in_sizes, int n_in,
                              void* d_out, int out_size) {
    const float* z    = (const float*)d_in[0];
    const float* emb  = (const float*)d_in[1];
    const float* nbuf = (const float*)d_in[2];
    const float* zavg = (const float*)d_in[3];
    float* out = (float*)d_out;

    float* q_out    = out + OFF_Q;
    float* dp_out   = out + OFF_DP;
    float* emb_out  = out + OFF_EMB;
    float* nnew_out = out + OFF_NNEW;
    float* zavg_out = out + OFF_ZAVG;

    // one-time init happens during the (uncaptured) correctness call
    static cudaStream_t s2 = nullptr;
    static cudaEvent_t evA = nullptr, evB = nullptr, evC = nullptr, evD = nullptr;
    if (!s2) {
        cudaStreamCreateWithFlags(&s2, cudaStreamNonBlocking);
        cudaEventCreateWithFlags(&evA, cudaEventDisableTiming);
        cudaEventCreateWithFlags(&evB, cudaEventDisableTiming);
        cudaEventCreateWithFlags(&evC, cudaEventDisableTiming);
        cudaEventCreateWithFlags(&evD, cudaEventDisableTiming);
        cudaFuncSetAttribute(k_gemm, cudaFuncAttributeMaxDynamicSharedMemorySize, 3 * STG_SZ);
        cudaFuncSetAttribute(k_normalize_z, cudaFuncAttributeMaxDynamicSharedMemorySize, 67584);
        cudaFuncSetAttribute(k_gather_q, cudaFuncAttributeMaxDynamicSharedMemorySize, 65664);
    }

    // fork 1: normalize_cb (s2)  ||  normalize_z (main)
    cudaEventRecord(evA, 0);
    cudaStreamWaitEvent(s2, evA, 0);
    k_normalize_cb<<<Kv, 128, 0, s2>>>(emb);
    cudaEventRecord(evB, s2);

    k_normalize_z<<<512, 256, 67584>>>(z);
    cudaStreamWaitEvent(0, evB, 0);

    k_gemm<<<dim3(16, 128), 256, 3 * STG_SZ>>>();
    k_softmax<<<Nv, 256>>>(dp_out);
    k_rescue<<<Nv / 8, 256>>>();

    // fork 2: gather_q (s2)  ||  stats -> fill -> zavg_emb (main)
    cudaEventRecord(evC, 0);
    cudaStreamWaitEvent(s2, evC, 0);
    k_gather_q<<<512, 256, 65664, s2>>>(q_out);
    cudaEventRecord(evD, s2);

    k_stats<<<1, 1024>>>(nnew_out, nbuf);
    k_fill<<<64, 256>>>();
    k_zavg_emb<<<Kv, 512>>>(zavg_out, zavg, emb_out, nnew_out);
    cudaStreamWaitEvent(0, evD, 0);

    k_finalize<<<1, 1>>>(out);
}